// round 13
// baseline (speedup 1.0000x reference)
#include <cuda_runtime.h>
#include <cuda_bf16.h>

#define THREADS 256
#define NWARP   8
#define NBINS   2048     // shared histogram, packed counts: low16=rowA, high16=rowB
#define BPT     8        // bins per thread
#define CAP     1024     // per-row rank-path candidate cap (overlays hist)

// Scratch: boost factors (n <= 16384 supported; actual n = 4096)
__device__ float g_bf[16384];

__global__ void boost_kernel(const float* __restrict__ duty,
                             const int* __restrict__ kp, int n) {
    int i = blockIdx.x * blockDim.x + threadIdx.x;
    if (i < n) {
        float td = (float)(*kp) / (float)n;
        g_bf[i] = expf(td - duty[i]);   // boostStrength = 1.0
    }
}

// Monotone float -> uint key (fallback path only)
__device__ __forceinline__ unsigned f2key(float f) {
    unsigned u = __float_as_uint(f);
    return u ^ (unsigned)(((int)u >> 31) | 0x80000000);
}
__device__ __forceinline__ float key2f(unsigned k) {
    unsigned m = ((int)k < 0) ? 0x80000000u : 0xFFFFFFFFu;
    return __uint_as_float(k ^ m);
}

struct Sm {
    union {
        unsigned hist[NBINS];   // 8KB, dead after the in-register scan
        struct { unsigned A[CAP]; unsigned B[CAP]; } list;
    } u;
    unsigned wtot[NWARP];       // packed per-warp suffix totals
    unsigned sBinA, sKrA, sCntA, sNumA, sThrA;
    unsigned sBinB, sKrB, sCntB, sNumB, sThrB;
};

template <int NK>
__device__ __forceinline__ float fallback_select(const float (&b)[NK], unsigned k0,
                                                 Sm* s, int lane, int wid) {
    // Exact block-wide greedy bit-descent over monotone keys (rare path).
    unsigned thr = 0;
    for (int bb = 31; bb >= 0; bb--) {
        unsigned test = thr | (1u << bb);
        unsigned c = 0;
        #pragma unroll
        for (int e = 0; e < NK; e++) c += (f2key(b[e]) >= test) ? 1u : 0u;
        c = __reduce_add_sync(0xFFFFFFFFu, c);
        if (lane == 0) s->wtot[wid] = c;
        __syncthreads();
        unsigned cb = 0;
        #pragma unroll
        for (int j = 0; j < NWARP; j++) cb += s->wtot[j];
        if (cb >= k0) thr = test;
        __syncthreads();
    }
    return key2f(thr);
}

template <int EPV>  // float4 elements per thread PER ROW
__global__ __launch_bounds__(THREADS, 4)
void kwinner2_kernel(const float* __restrict__ x,
                     const int* __restrict__ kp,
                     float* __restrict__ out, int n, int rows) {
    const int rowA = blockIdx.x * 2;
    const int rowB = min(rowA + 1, rows - 1);
    const int t    = threadIdx.x;
    const int lane = t & 31;
    const int wid  = t >> 5;
    constexpr int NK = EPV * 4;

    __shared__ Sm s;

    // Zero packed histogram: two uint4 stores per thread
    ((uint4*)s.u.hist)[t]           = make_uint4(0, 0, 0, 0);
    ((uint4*)s.u.hist)[t + THREADS] = make_uint4(0, 0, 0, 0);

    const float4* xrowA = (const float4*)(x + (size_t)rowA * n);
    const float4* xrowB = (const float4*)(x + (size_t)rowB * n);
    const float4* bfv   = (const float4*)g_bf;

    // bf loaded ONCE, serves both rows. x not kept (reloaded in epilogue).
    float bA[NK], bB[NK];
    #pragma unroll
    for (int j = 0; j < EPV; j++) {
        int f = t + j * THREADS;
        float4 bf = bfv[f];
        float4 xa = xrowA[f];
        float4 xb = xrowB[f];
        bA[j*4+0] = xa.x * bf.x;  bB[j*4+0] = xb.x * bf.x;
        bA[j*4+1] = xa.y * bf.y;  bB[j*4+1] = xb.y * bf.y;
        bA[j*4+2] = xa.z * bf.z;  bB[j*4+2] = xb.z * bf.z;
        bA[j*4+3] = xa.w * bf.w;  bB[j*4+3] = xb.w * bf.w;
    }
    if (t == 0) {
        s.sNumA = 0; s.sCntA = 0xFFFFFFFFu;
        s.sNumB = 0; s.sCntB = 0xFFFFFFFFu;
    }
    __syncthreads();   // hist zeroed

    // Packed histogram of positive values: bin = float bits [30:20].
    // Row A counts in low 16 bits, row B in high 16 (each <= 4096, no overflow).
    #pragma unroll
    for (int e = 0; e < NK; e++) {
        unsigned uA = __float_as_uint(bA[e]);
        if ((int)uA >= 0) atomicAdd(&s.u.hist[uA >> 20], 1u);
        unsigned uB = __float_as_uint(bB[e]);
        if ((int)uB >= 0) atomicAdd(&s.u.hist[uB >> 20], 0x10000u);
    }
    __syncthreads();

    const unsigned k0 = (unsigned)__ldg(kp);

    // ONE packed suffix-count scan serves both rows.
    uint4 a4 = ((const uint4*)s.u.hist)[t * 2];
    uint4 b4 = ((const uint4*)s.u.hist)[t * 2 + 1];
    unsigned hh[BPT] = {a4.x, a4.y, a4.z, a4.w, b4.x, b4.y, b4.z, b4.w};
    unsigned tot = 0;
    #pragma unroll
    for (int i = 0; i < BPT; i++) tot += hh[i];   // packed add, halves independent

    unsigned v = tot;   // packed sum over lanes [lane..31]
    #pragma unroll
    for (int off = 1; off < 32; off <<= 1) {
        unsigned u = __shfl_down_sync(0xFFFFFFFFu, v, off);
        if (lane + off < 32) v += u;
    }
    if (lane == 0) s.wtot[wid] = v;
    __syncthreads();

    unsigned run = v - tot;                 // packed in-warp suffix above own chunk
    for (int j = wid + 1; j < NWARP; j++)
        run += s.wtot[j];
    unsigned runA = run & 0xFFFFu, runB = run >> 16;
    #pragma unroll
    for (int i = BPT - 1; i >= 0; i--) {
        unsigned hA = hh[i] & 0xFFFFu, hB = hh[i] >> 16;
        unsigned nxtA = runA;  runA += hA;
        if (runA >= k0 && nxtA < k0) {
            s.sBinA = (unsigned)(t * BPT + i);
            s.sKrA  = k0 - nxtA;
            s.sCntA = hA;
        }
        unsigned nxtB = runB;  runB += hB;
        if (runB >= k0 && nxtB < k0) {
            s.sBinB = (unsigned)(t * BPT + i);
            s.sKrB  = k0 - nxtB;
            s.sCntB = hB;
        }
    }
    __syncthreads();
    const unsigned binA = s.sBinA, krA = s.sKrA, C1A = s.sCntA;
    const unsigned binB = s.sBinB, krB = s.sKrB, C1B = s.sCntB;
    const bool okA = (C1A <= CAP), okB = (C1B <= CAP);

    // Compact crossing-bin candidates for both rows (overlays hist).
    #pragma unroll
    for (int e = 0; e < NK; e++) {
        unsigned uA = __float_as_uint(bA[e]);
        if (okA && (uA >> 20) == binA)       // negatives can't match (bin < 2048)
            s.u.list.A[atomicAdd(&s.sNumA, 1u)] = uA;
        unsigned uB = __float_as_uint(bB[e]);
        if (okB && (uB >> 20) == binB)
            s.u.list.B[atomicAdd(&s.sNumB, 1u)] = uB;
    }
    __syncthreads();

    // Concurrent parallel rank: warps 0-3 -> row A, warps 4-7 -> row B.
    // Raw-bit uint order == float order for positives.
    if (wid < 4) {
        if (okA) {
            const unsigned C = s.sNumA;
            for (unsigned i = (unsigned)t; i < C; i += THREADS / 2) {
                unsigned ki = s.u.list.A[i];
                unsigned gt = 0, ge = 0;
                #pragma unroll 4
                for (unsigned j = 0; j < C; j++) {
                    unsigned lj = s.u.list.A[j];
                    gt += (lj > ki)  ? 1u : 0u;
                    ge += (lj >= ki) ? 1u : 0u;
                }
                if (gt < krA && ge >= krA) s.sThrA = ki;
            }
        }
    } else {
        if (okB) {
            const unsigned C = s.sNumB;
            for (unsigned i = (unsigned)(t - THREADS / 2); i < C; i += THREADS / 2) {
                unsigned ki = s.u.list.B[i];
                unsigned gt = 0, ge = 0;
                #pragma unroll 4
                for (unsigned j = 0; j < C; j++) {
                    unsigned lj = s.u.list.B[j];
                    gt += (lj > ki)  ? 1u : 0u;
                    ge += (lj >= ki) ? 1u : 0u;
                }
                if (gt < krB && ge >= krB) s.sThrB = ki;
            }
        }
    }
    __syncthreads();

    float thrA = okA ? __uint_as_float(s.sThrA) : 0.0f;
    float thrB = okB ? __uint_as_float(s.sThrB) : 0.0f;
    // Exactness fallback per row (positives < k0 or giant bin); block-wide,
    // uniform branch. Never taken on benchmark data.
    if (!okA) thrA = fallback_select<NK>(bA, k0, &s, lane, wid);
    if (!okB) thrB = fallback_select<NK>(bB, k0, &s, lane, wid);

    // Output: EXACT passthrough of x (reloaded; L2-hot), float >= mask
    // (identical semantics to the reference's boosted >= bottom).
    float4* orowA = (float4*)(out + (size_t)rowA * n);
    float4* orowB = (float4*)(out + (size_t)rowB * n);
    #pragma unroll
    for (int j = 0; j < EPV; j++) {
        int f = t + j * THREADS;
        float4 xa = xrowA[f];
        float4 oa;
        oa.x = (bA[j*4+0] >= thrA) ? xa.x : 0.0f;
        oa.y = (bA[j*4+1] >= thrA) ? xa.y : 0.0f;
        oa.z = (bA[j*4+2] >= thrA) ? xa.z : 0.0f;
        oa.w = (bA[j*4+3] >= thrA) ? xa.w : 0.0f;
        orowA[f] = oa;
        float4 xb = xrowB[f];
        float4 ob;
        ob.x = (bB[j*4+0] >= thrB) ? xb.x : 0.0f;
        ob.y = (bB[j*4+1] >= thrB) ? xb.y : 0.0f;
        ob.z = (bB[j*4+2] >= thrB) ? xb.z : 0.0f;
        ob.w = (bB[j*4+3] >= thrB) ? xb.w : 0.0f;
        orowB[f] = ob;
    }
}

extern "C" void kernel_launch(void* const* d_in, const int* in_sizes, int n_in,
                              void* d_out, int out_size) {
    const float* x    = (const float*)d_in[0];
    const float* duty = (const float*)d_in[1];
    const int*   kp   = (const int*)d_in[2];
    float*       out  = (float*)d_out;

    int n    = in_sizes[1];          // 4096
    int rows = in_sizes[0] / n;      // 8192

    boost_kernel<<<(n + 255) / 256, 256>>>(duty, kp, n);

    int pairs = (rows + 1) / 2;
    int epv   = n / (THREADS * 4);
    switch (epv) {
        case 1:  kwinner2_kernel<1><<<pairs, THREADS>>>(x, kp, out, n, rows);  break;
        case 2:  kwinner2_kernel<2><<<pairs, THREADS>>>(x, kp, out, n, rows);  break;
        case 4:  kwinner2_kernel<4><<<pairs, THREADS>>>(x, kp, out, n, rows);  break;
        case 8:  kwinner2_kernel<8><<<pairs, THREADS>>>(x, kp, out, n, rows);  break;
        default: break; // unsupported shape (not expected for this problem)
    }
}

// round 14
// speedup vs baseline: 1.0612x; 1.0612x over previous
#include <cuda_runtime.h>
#include <cuda_bf16.h>

#define THREADS 256
#define NWARP   8
#define NBINS   2048     // shared histogram, packed counts: low16=rowA, high16=rowB
#define BPT     8        // bins per thread
#define CAP     1024     // per-row rank-path candidate cap (overlays hist)

// Scratch: boost factors (n <= 16384 supported; actual n = 4096)
__device__ float g_bf[16384];

__global__ void boost_kernel(const float* __restrict__ duty,
                             const int* __restrict__ kp, int n) {
    int i = blockIdx.x * blockDim.x + threadIdx.x;
    if (i < n) {
        float td = (float)(*kp) / (float)n;
        g_bf[i] = expf(td - duty[i]);   // boostStrength = 1.0
    }
}

// Monotone float -> uint key (fallback path only)
__device__ __forceinline__ unsigned f2key(float f) {
    unsigned u = __float_as_uint(f);
    return u ^ (unsigned)(((int)u >> 31) | 0x80000000);
}
__device__ __forceinline__ float key2f(unsigned k) {
    unsigned m = ((int)k < 0) ? 0x80000000u : 0xFFFFFFFFu;
    return __uint_as_float(k ^ m);
}

struct Sm {
    union {
        unsigned hist[NBINS];   // 8KB, dead after the in-register scan
        struct { unsigned A[CAP]; unsigned B[CAP]; } list;
    } u;
    unsigned wtot[NWARP];       // packed per-warp suffix totals
    unsigned sBinA, sKrA, sCntA, sNumA, sThrA;
    unsigned sBinB, sKrB, sCntB, sNumB, sThrB;
};

template <int NK>
__device__ __forceinline__ float fallback_select(const float (&b)[NK], unsigned k0,
                                                 Sm* s, int lane, int wid) {
    // Exact block-wide greedy bit-descent over monotone keys (rare path).
    unsigned thr = 0;
    for (int bb = 31; bb >= 0; bb--) {
        unsigned test = thr | (1u << bb);
        unsigned c = 0;
        #pragma unroll
        for (int e = 0; e < NK; e++) c += (f2key(b[e]) >= test) ? 1u : 0u;
        c = __reduce_add_sync(0xFFFFFFFFu, c);
        if (lane == 0) s->wtot[wid] = c;
        __syncthreads();
        unsigned cb = 0;
        #pragma unroll
        for (int j = 0; j < NWARP; j++) cb += s->wtot[j];
        if (cb >= k0) thr = test;
        __syncthreads();
    }
    return key2f(thr);
}

template <int EPV>  // float4 elements per thread PER ROW
__global__ __launch_bounds__(THREADS, 3)
void kwinner2_kernel(const float* __restrict__ x,
                     const int* __restrict__ kp,
                     float* __restrict__ out, int n, int rows) {
    const int rowA = blockIdx.x * 2;
    const int rowB = min(rowA + 1, rows - 1);
    const int t    = threadIdx.x;
    const int lane = t & 31;
    const int wid  = t >> 5;
    constexpr int NK = EPV * 4;

    __shared__ Sm s;

    // Zero packed histogram: two uint4 stores per thread
    ((uint4*)s.u.hist)[t]           = make_uint4(0, 0, 0, 0);
    ((uint4*)s.u.hist)[t + THREADS] = make_uint4(0, 0, 0, 0);

    const float4* xrowA = (const float4*)(x + (size_t)rowA * n);
    const float4* xrowB = (const float4*)(x + (size_t)rowB * n);
    const float4* bfv   = (const float4*)g_bf;

    // bf loaded ONCE, serves both rows. x not kept (reloaded in epilogue).
    float bA[NK], bB[NK];
    #pragma unroll
    for (int j = 0; j < EPV; j++) {
        int f = t + j * THREADS;
        float4 bf = bfv[f];
        float4 xa = xrowA[f];
        float4 xb = xrowB[f];
        bA[j*4+0] = xa.x * bf.x;  bB[j*4+0] = xb.x * bf.x;
        bA[j*4+1] = xa.y * bf.y;  bB[j*4+1] = xb.y * bf.y;
        bA[j*4+2] = xa.z * bf.z;  bB[j*4+2] = xb.z * bf.z;
        bA[j*4+3] = xa.w * bf.w;  bB[j*4+3] = xb.w * bf.w;
    }
    if (t == 0) {
        s.sNumA = 0; s.sCntA = 0xFFFFFFFFu;
        s.sNumB = 0; s.sCntB = 0xFFFFFFFFu;
    }
    __syncthreads();   // hist zeroed

    // Packed histogram of positive values: bin = float bits [30:20].
    // Row A counts in low 16 bits, row B in high 16 (each <= 4096, no overflow).
    #pragma unroll
    for (int e = 0; e < NK; e++) {
        unsigned uA = __float_as_uint(bA[e]);
        if ((int)uA >= 0) atomicAdd(&s.u.hist[uA >> 20], 1u);
        unsigned uB = __float_as_uint(bB[e]);
        if ((int)uB >= 0) atomicAdd(&s.u.hist[uB >> 20], 0x10000u);
    }
    __syncthreads();

    const unsigned k0 = (unsigned)__ldg(kp);

    // ONE packed suffix-count scan serves both rows.
    uint4 a4 = ((const uint4*)s.u.hist)[t * 2];
    uint4 b4 = ((const uint4*)s.u.hist)[t * 2 + 1];
    unsigned hh[BPT] = {a4.x, a4.y, a4.z, a4.w, b4.x, b4.y, b4.z, b4.w};
    unsigned tot = 0;
    #pragma unroll
    for (int i = 0; i < BPT; i++) tot += hh[i];   // packed add, halves independent

    unsigned v = tot;   // packed sum over lanes [lane..31]
    #pragma unroll
    for (int off = 1; off < 32; off <<= 1) {
        unsigned u = __shfl_down_sync(0xFFFFFFFFu, v, off);
        if (lane + off < 32) v += u;
    }
    if (lane == 0) s.wtot[wid] = v;
    __syncthreads();

    unsigned run = v - tot;                 // packed in-warp suffix above own chunk
    for (int j = wid + 1; j < NWARP; j++)
        run += s.wtot[j];
    unsigned runA = run & 0xFFFFu, runB = run >> 16;
    #pragma unroll
    for (int i = BPT - 1; i >= 0; i--) {
        unsigned hA = hh[i] & 0xFFFFu, hB = hh[i] >> 16;
        unsigned nxtA = runA;  runA += hA;
        if (runA >= k0 && nxtA < k0) {
            s.sBinA = (unsigned)(t * BPT + i);
            s.sKrA  = k0 - nxtA;
            s.sCntA = hA;
        }
        unsigned nxtB = runB;  runB += hB;
        if (runB >= k0 && nxtB < k0) {
            s.sBinB = (unsigned)(t * BPT + i);
            s.sKrB  = k0 - nxtB;
            s.sCntB = hB;
        }
    }
    __syncthreads();
    const unsigned binA = s.sBinA, krA = s.sKrA, C1A = s.sCntA;
    const unsigned binB = s.sBinB, krB = s.sKrB, C1B = s.sCntB;
    const bool okA = (C1A <= CAP), okB = (C1B <= CAP);

    // Compact crossing-bin candidates for both rows (overlays hist).
    #pragma unroll
    for (int e = 0; e < NK; e++) {
        unsigned uA = __float_as_uint(bA[e]);
        if (okA && (uA >> 20) == binA)       // negatives can't match (bin < 2048)
            s.u.list.A[atomicAdd(&s.sNumA, 1u)] = uA;
        unsigned uB = __float_as_uint(bB[e]);
        if (okB && (uB >> 20) == binB)
            s.u.list.B[atomicAdd(&s.sNumB, 1u)] = uB;
    }
    __syncthreads();

    // Concurrent parallel rank: warps 0-3 -> row A, warps 4-7 -> row B.
    // Raw-bit uint order == float order for positives.
    if (wid < 4) {
        if (okA) {
            const unsigned C = s.sNumA;
            for (unsigned i = (unsigned)t; i < C; i += THREADS / 2) {
                unsigned ki = s.u.list.A[i];
                unsigned gt = 0, ge = 0;
                #pragma unroll 4
                for (unsigned j = 0; j < C; j++) {
                    unsigned lj = s.u.list.A[j];
                    gt += (lj > ki)  ? 1u : 0u;
                    ge += (lj >= ki) ? 1u : 0u;
                }
                if (gt < krA && ge >= krA) s.sThrA = ki;
            }
        }
    } else {
        if (okB) {
            const unsigned C = s.sNumB;
            for (unsigned i = (unsigned)(t - THREADS / 2); i < C; i += THREADS / 2) {
                unsigned ki = s.u.list.B[i];
                unsigned gt = 0, ge = 0;
                #pragma unroll 4
                for (unsigned j = 0; j < C; j++) {
                    unsigned lj = s.u.list.B[j];
                    gt += (lj > ki)  ? 1u : 0u;
                    ge += (lj >= ki) ? 1u : 0u;
                }
                if (gt < krB && ge >= krB) s.sThrB = ki;
            }
        }
    }
    __syncthreads();

    float thrA = okA ? __uint_as_float(s.sThrA) : 0.0f;
    float thrB = okB ? __uint_as_float(s.sThrB) : 0.0f;
    // Exactness fallback per row (positives < k0 or giant bin); block-wide,
    // uniform branch. Never taken on benchmark data.
    if (!okA) thrA = fallback_select<NK>(bA, k0, &s, lane, wid);
    if (!okB) thrB = fallback_select<NK>(bB, k0, &s, lane, wid);

    // Output: EXACT passthrough of x (reloaded; L2-hot), float >= mask
    // (identical semantics to the reference's boosted >= bottom).
    // Two sequential per-row loops: xa/xb never co-resident -> lower reg peak.
    float4* orowA = (float4*)(out + (size_t)rowA * n);
    #pragma unroll
    for (int j = 0; j < EPV; j++) {
        int f = t + j * THREADS;
        float4 xa = xrowA[f];
        float4 oa;
        oa.x = (bA[j*4+0] >= thrA) ? xa.x : 0.0f;
        oa.y = (bA[j*4+1] >= thrA) ? xa.y : 0.0f;
        oa.z = (bA[j*4+2] >= thrA) ? xa.z : 0.0f;
        oa.w = (bA[j*4+3] >= thrA) ? xa.w : 0.0f;
        orowA[f] = oa;
    }
    float4* orowB = (float4*)(out + (size_t)rowB * n);
    #pragma unroll
    for (int j = 0; j < EPV; j++) {
        int f = t + j * THREADS;
        float4 xb = xrowB[f];
        float4 ob;
        ob.x = (bB[j*4+0] >= thrB) ? xb.x : 0.0f;
        ob.y = (bB[j*4+1] >= thrB) ? xb.y : 0.0f;
        ob.z = (bB[j*4+2] >= thrB) ? xb.z : 0.0f;
        ob.w = (bB[j*4+3] >= thrB) ? xb.w : 0.0f;
        orowB[f] = ob;
    }
}

extern "C" void kernel_launch(void* const* d_in, const int* in_sizes, int n_in,
                              void* d_out, int out_size) {
    const float* x    = (const float*)d_in[0];
    const float* duty = (const float*)d_in[1];
    const int*   kp   = (const int*)d_in[2];
    float*       out  = (float*)d_out;

    int n    = in_sizes[1];          // 4096
    int rows = in_sizes[0] / n;      // 8192

    boost_kernel<<<(n + 255) / 256, 256>>>(duty, kp, n);

    int pairs = (rows + 1) / 2;
    int epv   = n / (THREADS * 4);
    switch (epv) {
        case 1:  kwinner2_kernel<1><<<pairs, THREADS>>>(x, kp, out, n, rows);  break;
        case 2:  kwinner2_kernel<2><<<pairs, THREADS>>>(x, kp, out, n, rows);  break;
        case 4:  kwinner2_kernel<4><<<pairs, THREADS>>>(x, kp, out, n, rows);  break;
        case 8:  kwinner2_kernel<8><<<pairs, THREADS>>>(x, kp, out, n, rows);  break;
        default: break; // unsupported shape (not expected for this problem)
    }
}